// round 17
// speedup vs baseline: 3.7645x; 1.0068x over previous
#include <cuda_runtime.h>
#include <cuda_fp16.h>
#include <math.h>
#include <stdint.h>

// ---------------------------------------------------------------------------
// MSDeformAttn transformer encoder (6 layers).
// All GEMMs full-fp16 tcgen05 kind::f16 (fp32 accum), 1 MMA per K64 chunk.
// K=256: persistent-B (B resident 64KB, 2 CTAs/SM), pipelined A loads.
// val + off/attn GEMMs fused into ONE launch (5 column groups).
// W2: streaming. Residual mirrored fp16. sm_103a guarded; SIMT fallback.
// D=256, NH=8, NL=4, NP=4, DH=32, DFF=1024, B=2, S=21760.
// ---------------------------------------------------------------------------

#define D_MODEL 256
#define NH 8
#define DFF 1024
#define NLAYERS 6
#define BATCH 2
#define S_TOTAL 21760
#define M_TOT (BATCH * S_TOTAL)   // 43520 rows; 340 M-tiles of 128

#if defined(__CUDA_ARCH_FEAT_SM103_ALL) || defined(__CUDA_ARCH_FEAT_SM100_ALL) || defined(__CUDA_ARCH_FEAT_SM101_ALL)
#define HAS_TCGEN05 1
#else
#define HAS_TCGEN05 0
#endif

// Scratch (allocation-free: __device__ globals)
__device__ __half g_posh[M_TOT * D_MODEL];        // fp16 positional stream
__device__ __half g_outh[M_TOT * D_MODEL];        // fp16 residual stream
__device__ __half g_qh[M_TOT * D_MODEL];          // fp16 (out + pos)
__device__ __half g_valh[M_TOT * D_MODEL];        // fp16 value tensor
__device__ float  g_offawl[M_TOT * 384];          // [off 256 | awl 128] per row
__device__ __half g_samph[M_TOT * D_MODEL];       // fp16 sampled tensor
__device__ __half g_tmph[M_TOT * D_MODEL];        // fp16 branch output
__device__ __half g_ffh[M_TOT * DFF];             // fp16 FF hidden
__device__ float  g_biasva[NLAYERS * 640];        // [bval 256 | boff 256 | battn 128]

// Transposed fp16 weights: per layer 753664 elements
#define WT_LAYER 753664
__device__ __half g_wth[NLAYERS * WT_LAYER];
#define WT_VAL  0
#define WT_OFF  65536
#define WT_ATTN 131072
#define WT_OUT  163840
#define WT_W1   229376
#define WT_W2   491520

// ---------------------------------------------------------------------------
// PTX helpers
// ---------------------------------------------------------------------------
__device__ __forceinline__ uint32_t elect_one_pred() {
    uint32_t pred;
    asm volatile(
        "{\n\t.reg .pred p;\n\telect.sync _|p, 0xFFFFFFFF;\n\t"
        "selp.b32 %0, 1, 0, p;\n\t}" : "=r"(pred));
    return pred;
}
__device__ __forceinline__ uint32_t smem_to_u32(const void* p) {
    uint32_t a;
    asm("{ .reg .u64 t; cvta.to.shared.u64 t, %1; cvt.u32.u64 %0, t; }"
        : "=r"(a) : "l"(p));
    return a;
}

#define TCGEN05_ALLOC(addr, n) \
    asm volatile("tcgen05.alloc.cta_group::1.sync.aligned.shared::cta.b32 [%0], %1;" \
                 :: "r"((uint32_t)(addr)), "r"((uint32_t)(n)) : "memory")
#define TCGEN05_DEALLOC(tmem, n) \
    asm volatile("tcgen05.dealloc.cta_group::1.sync.aligned.b32 %0, %1;" \
                 :: "r"(tmem), "r"((uint32_t)(n)))
#define TCGEN05_RELINQ() \
    asm volatile("tcgen05.relinquish_alloc_permit.cta_group::1.sync.aligned;")
#define TCGEN05_COMMIT(mbar) \
    asm volatile("tcgen05.commit.cta_group::1.mbarrier::arrive::one.shared::cluster.b64 [%0];" \
                 :: "r"((uint32_t)(mbar)) : "memory")
#define TCGEN05_FENCE_AFTER() \
    asm volatile("tcgen05.fence::after_thread_sync;" ::: "memory")
#define TCGEN05_FENCE_BEFORE() \
    asm volatile("tcgen05.fence::before_thread_sync;" ::: "memory")
#define TCGEN05_WAIT_LD() \
    asm volatile("tcgen05.wait::ld.sync.aligned;" ::: "memory")
#define FENCE_PROXY_ASYNC() \
    asm volatile("fence.proxy.async.shared::cta;" ::: "memory")
#define MBARRIER_INIT(mbar, cnt) \
    asm volatile("mbarrier.init.shared.b64 [%0], %1;" \
                 :: "r"((uint32_t)(mbar)), "r"((uint32_t)(cnt)) : "memory")
#define MBARRIER_INVAL(mbar) \
    asm volatile("mbarrier.inval.shared.b64 [%0];" :: "r"((uint32_t)(mbar)) : "memory")

#define MBARRIER_WAIT_PARITY(mbar, parity) do {                               \
    uint32_t _m = (uint32_t)(mbar);                                           \
    uint32_t _p = (uint32_t)(parity);                                         \
    asm volatile(                                                             \
        "{\n\t.reg .pred P1;\n\t"                                             \
        "WAIT_LOOP_%=:\n\t"                                                   \
        "mbarrier.try_wait.parity.acquire.cta.shared::cta.b64 P1, [%0], %1, 0x989680;\n\t" \
        "@P1 bra.uni WAIT_DONE_%=;\n\t"                                       \
        "bra.uni WAIT_LOOP_%=;\n\t"                                           \
        "WAIT_DONE_%=:\n\t}"                                                  \
        :: "r"(_m), "r"(_p) : "memory");                                      \
} while (0)

// fp16 SS MMA (fp32 accum), cta_group::1
#define TCGEN05_MMA_F16_SS(d, ad, bd, id, en) do {                            \
    uint32_t _e = (en) ? 1u : 0u; uint32_t _z = 0;                            \
    asm volatile(                                                             \
        "{\n\t.reg .pred p;\n\tsetp.ne.u32 p, %5, 0;\n\t"                     \
        "tcgen05.mma.cta_group::1.kind::f16 [%0], %1, %2, %3, {%4,%4,%4,%4}, p;\n\t}" \
        :: "r"(d), "l"(ad), "l"(bd), "r"(id), "r"(_z), "r"(_e) : "memory");   \
} while (0)

#define TCGEN05_LD32(r, addr)                                                 \
    asm volatile(                                                             \
        "tcgen05.ld.sync.aligned.32x32b.x32.b32 "                             \
        "{%0, %1, %2, %3, %4, %5, %6, %7, "                                   \
        " %8, %9, %10, %11, %12, %13, %14, %15, "                             \
        " %16, %17, %18, %19, %20, %21, %22, %23, "                           \
        " %24, %25, %26, %27, %28, %29, %30, %31}, [%32];"                    \
        : "=r"((r)[0]),  "=r"((r)[1]),  "=r"((r)[2]),  "=r"((r)[3]),          \
          "=r"((r)[4]),  "=r"((r)[5]),  "=r"((r)[6]),  "=r"((r)[7]),          \
          "=r"((r)[8]),  "=r"((r)[9]),  "=r"((r)[10]), "=r"((r)[11]),         \
          "=r"((r)[12]), "=r"((r)[13]), "=r"((r)[14]), "=r"((r)[15]),         \
          "=r"((r)[16]), "=r"((r)[17]), "=r"((r)[18]), "=r"((r)[19]),         \
          "=r"((r)[20]), "=r"((r)[21]), "=r"((r)[22]), "=r"((r)[23]),         \
          "=r"((r)[24]), "=r"((r)[25]), "=r"((r)[26]), "=r"((r)[27]),         \
          "=r"((r)[28]), "=r"((r)[29]), "=r"((r)[30]), "=r"((r)[31])          \
        : "r"(addr))

// SW128 K-major smem descriptor: layout=2, version=1, SBO=64, LBO=1
__device__ __forceinline__ uint64_t make_sw128_desc(uint32_t addr) {
    const uint64_t base = (uint64_t(2) << 61) | (uint64_t(1) << 46)
                        | (uint64_t(64) << 32) | (uint64_t(1) << 16);
    return base | ((uint64_t)(addr >> 4) & 0x3FFF);
}

#define TCG_IDESC 0x8200010u

// Epilogue store of 4 consecutive cols (float or half)
template <int RELU, int OUTH>
__device__ __forceinline__ void epi_store4(float* Cf, size_t idx, float4 o) {
    if (RELU) {
        o.x = fmaxf(o.x, 0.f); o.y = fmaxf(o.y, 0.f);
        o.z = fmaxf(o.z, 0.f); o.w = fmaxf(o.w, 0.f);
    }
    if (OUTH) {
        __half2 h0 = __halves2half2(__float2half_rn(o.x), __float2half_rn(o.y));
        __half2 h1 = __halves2half2(__float2half_rn(o.z), __float2half_rn(o.w));
        uint2 u; u.x = *(uint32_t*)&h0; u.y = *(uint32_t*)&h1;
        *(uint2*)((__half*)Cf + idx) = u;
    } else {
        *(float4*)(Cf + idx) = o;
    }
}

// ---------------------------------------------------------------------------
// Streaming GEMM, full fp16: used for W2 (K=1024, A = ffh half).
// ---------------------------------------------------------------------------
#define HOFF_AH 0
#define HOFF_BH 16384
#define HSTAGE  32768
#define TCGH_SMEM (1024 + 2 * HSTAGE)   // 66560

template <int RELU, int OUTH>
__global__ __launch_bounds__(256)
void tc_gemm_h(const __half* __restrict__ A,
               const __half* __restrict__ WH,
               const float* __restrict__ bias, float* __restrict__ C,
               int M, int N, int K) {
    extern __shared__ char smem[];
    const int tid  = threadIdx.x;
    const int brow = blockIdx.x * 128;
    const int bcol = blockIdx.y * 128;

    const int lr = tid >> 3;
    const int c8 = (tid & 7) * 8;
    const __half* Ab  = A  + (size_t)(brow + lr) * K + c8;
    const __half* BHb = WH + (size_t)(bcol + lr) * K + c8;
    const int KT = K >> 6;

    uint4 ua[4], bh[4];

#define HLDG_TILE(kt) do {                                                    \
    int _k = (kt) * 64;                                                       \
    _Pragma("unroll")                                                         \
    for (int i = 0; i < 4; i++) {                                             \
        size_t ro = (size_t)(i * 32) * K + _k;                                \
        ua[i] = *(const uint4*)(Ab + ro);                                     \
        bh[i] = *(const uint4*)(BHb + ro);                                    \
    }                                                                         \
} while (0)

#if HAS_TCGEN05
    const uint32_t sbase = smem_to_u32(smem);
    const int wid  = tid >> 5;
    const int lane = tid & 31;

    const uint32_t TMEMP = sbase;
    const uint32_t MBAR0 = sbase + 8;
    const uint32_t MBAR1 = sbase + 16;
    const uint32_t STG0  = sbase + 1024;

    if (wid == 0) TCGEN05_ALLOC(TMEMP, 128);
    if (tid == 0) { MBARRIER_INIT(MBAR0, 1); MBARRIER_INIT(MBAR1, 1); }
    __syncthreads();
    uint32_t tmem;
    asm volatile("ld.shared.b32 %0, [%1];" : "=r"(tmem) : "r"(TMEMP));
    if (wid == 0) TCGEN05_RELINQ();

    uint32_t swoff[4];
#pragma unroll
    for (int i = 0; i < 4; i++) {
        uint32_t off = (uint32_t)(i * 32 + lr) * 128 + (tid & 7) * 16;
        swoff[i] = off ^ ((off >> 3) & 0x70);
    }

    int ph0 = 0, ph1 = 0;

#define HSTS_TILE(stoff) do {                                                 \
    char* _sb = smem + 1024 + (stoff);                                        \
    _Pragma("unroll")                                                         \
    for (int i = 0; i < 4; i++) {                                             \
        *(uint4*)(_sb + HOFF_AH + swoff[i]) = ua[i];                          \
        *(uint4*)(_sb + HOFF_BH + swoff[i]) = bh[i];                          \
    }                                                                         \
} while (0)

    HLDG_TILE(0);
    HSTS_TILE(0);
    FENCE_PROXY_ASYNC();
    __syncthreads();

    for (int kt = 0; kt < KT; kt++) {
        int s = kt & 1;
        bool have_next = (kt + 1 < KT);
        if (have_next) HLDG_TILE(kt + 1);

        if (wid == 0) {
            if (elect_one_pred()) {
                uint32_t sb = STG0 + s * HSTAGE;
                uint64_t dah = make_sw128_desc(sb + HOFF_AH);
                uint64_t dbh = make_sw128_desc(sb + HOFF_BH);
#pragma unroll
                for (int ks = 0; ks < 4; ks++) {
                    TCGEN05_MMA_F16_SS(tmem, dah + ks * 2, dbh + ks * 2,
                                       TCG_IDESC, (kt > 0) || (ks > 0));
                }
                TCGEN05_COMMIT(s == 0 ? MBAR0 : MBAR1);
            }
        }

        if (have_next) {
            int ns = s ^ 1;
            if (kt >= 1) {
                if (ns == 0) { MBARRIER_WAIT_PARITY(MBAR0, ph0); ph0 ^= 1; }
                else         { MBARRIER_WAIT_PARITY(MBAR1, ph1); ph1 ^= 1; }
            }
            HSTS_TILE(ns * HSTAGE);
            FENCE_PROXY_ASYNC();
            __syncthreads();
        }
    }

    if (((KT - 1) & 1) == 0) { MBARRIER_WAIT_PARITY(MBAR0, ph0); }
    else                     { MBARRIER_WAIT_PARITY(MBAR1, ph1); }
    TCGEN05_FENCE_AFTER();

    {
        int colbase = (wid >> 2) * 64;
        uint32_t d0[32], d1[32];
        TCGEN05_LD32(d0, tmem + colbase);
        TCGEN05_LD32(d1, tmem + colbase + 32);
        TCGEN05_WAIT_LD();
        TCGEN05_FENCE_BEFORE();

        int r = brow + (wid & 3) * 32 + lane;
        size_t base = (size_t)r * N + bcol + colbase;
        const float* bb = bias + bcol + colbase;
#pragma unroll
        for (int c = 0; c < 32; c += 4) {
            float4 o;
            o.x = __uint_as_float(d0[c + 0]) + bb[c + 0];
            o.y = __uint_as_float(d0[c + 1]) + bb[c + 1];
            o.z = __uint_as_float(d0[c + 2]) + bb[c + 2];
            o.w = __uint_as_float(d0[c + 3]) + bb[c + 3];
            epi_store4<RELU, OUTH>(C, base + c, o);
        }
#pragma unroll
        for (int c = 0; c < 32; c += 4) {
            float4 o;
            o.x = __uint_as_float(d1[c + 0]) + bb[32 + c + 0];
            o.y = __uint_as_float(d1[c + 1]) + bb[32 + c + 1];
            o.z = __uint_as_float(d1[c + 2]) + bb[32 + c + 2];
            o.w = __uint_as_float(d1[c + 3]) + bb[32 + c + 3];
            epi_store4<RELU, OUTH>(C, base + 32 + c, o);
        }
    }

    __syncthreads();
    if (tid == 0) { MBARRIER_INVAL(MBAR0); MBARRIER_INVAL(MBAR1); }
    __syncthreads();
    if (wid == 0) TCGEN05_DEALLOC(tmem, 128);

#else  // SIMT fallback
    float (*As)[132] = (float(*)[132])(smem);
    float (*Bs)[132] = (float(*)[132])(smem + 64 * 132 * 4);

    int ty = (tid >> 4) * 8;
    int tx = (tid & 15) * 8;

    float acc[8][8];
#pragma unroll
    for (int i = 0; i < 8; i++)
#pragma unroll
        for (int j = 0; j < 8; j++) acc[i][j] = 0.f;

    for (int kt = 0; kt < KT; kt++) {
        HLDG_TILE(kt);
        __syncthreads();
#pragma unroll
        for (int i = 0; i < 4; i++) {
            int r = i * 32 + lr;
            const __half* ha = (const __half*)&ua[i];
            const __half* hh = (const __half*)&bh[i];
#pragma unroll
            for (int j = 0; j < 8; j++) {
                As[c8 + j][r] = __half2float(ha[j]);
                Bs[c8 + j][r] = __half2float(hh[j]);
            }
        }
        __syncthreads();
#pragma unroll 16
        for (int k = 0; k < 64; k++) {
            float av[8], bv[8];
#pragma unroll
            for (int i = 0; i < 8; i++) { av[i] = As[k][ty + i]; bv[i] = Bs[k][tx + i]; }
#pragma unroll
            for (int i = 0; i < 8; i++)
#pragma unroll
                for (int j = 0; j < 8; j++)
                    acc[i][j] += av[i] * bv[j];
        }
    }

    int row = brow + ty;
    int col = bcol + tx;
#pragma unroll
    for (int i = 0; i < 8; i++) {
#pragma unroll
        for (int j = 0; j < 8; j++) {
            float v = acc[i][j] + bias[col + j];
            if (RELU) v = fmaxf(v, 0.f);
            if (OUTH) ((__half*)C)[(size_t)(row + i) * N + col + j] = __float2half_rn(v);
            else      C[(size_t)(row + i) * N + col + j] = v;
        }
    }
#endif
}

// ---------------------------------------------------------------------------
// Persistent-B GEMM, full fp16, 1 MMA per K64 chunk. K=256.
// FUSED=0: single (A, C, N) GEMM over col groups (Wout / W1).
// FUSED=1: 5-col-group fused val+offattn:
//   col 0..1 : A = Aa (outh), C = Ca (valh, half, N=256), bias rows 0..255
//   col 2..4 : A = Ab (qh),   C = Cb (offawl, f32, N=384), bias rows 256..639
// A loads software-pipelined across chunk and tile boundaries.
// SMEM: 1024 hdr + 65536 B + 2x16384 A = 99328 -> 2 CTAs/SM.
// ---------------------------------------------------------------------------
#define PERS_SMEM_H 99328
#define MT_TILES (M_TOT / 128)   // 340

template <int RELU, int OUTH, int FUSED>
__global__ __launch_bounds__(256)
void tc_gemm_pers(const __half* __restrict__ Aa, const __half* __restrict__ Ab,
                  const __half* __restrict__ WH,
                  const float* __restrict__ bias,
                  float* __restrict__ Ca, float* __restrict__ Cb,
                  int Nin, int CPC) {
    extern __shared__ char smem[];
    const int tid = threadIdx.x;
    const int K = 256;
    const int col = blockIdx.x / CPC;
    const int cid = blockIdx.x % CPC;
    constexpr int ASTAGE = 16384;

    // Per-CTA selection (uniform)
    const bool grpA = !FUSED || (col < 2);
    const __half* A = grpA ? Aa : Ab;
    float* C        = (FUSED && !grpA) ? Cb : Ca;
    const int N     = FUSED ? (grpA ? 256 : 384) : Nin;
    const int bcolW = col * 128;                            // rows into weights/bias
    const int bcolC = FUSED ? (grpA ? col * 128 : (col - 2) * 128) : col * 128;
    const bool outH = FUSED ? grpA : (OUTH != 0);

    const int lr  = tid >> 3;
    const int c16 = tid & 7;
    const uint32_t swr = (uint32_t)lr * 128 + (uint32_t)((c16 ^ (lr & 7)) * 16);

#if HAS_TCGEN05
    const uint32_t sbase = smem_to_u32(smem);
    const int wid = tid >> 5, lane = tid & 31;
    const uint32_t TMEMP = sbase;
    const uint32_t MBAR0 = sbase + 8;
    const uint32_t MBAR1 = sbase + 16;
    const uint32_t BH_S  = sbase + 1024;
    const uint32_t AST   = BH_S + 65536;

    if (wid == 0) TCGEN05_ALLOC(TMEMP, 128);
    if (tid == 0) { MBARRIER_INIT(MBAR0, 1); MBARRIER_INIT(MBAR1, 1); }
    __syncthreads();
    uint32_t tmem;
    asm volatile("ld.shared.b32 %0, [%1];" : "=r"(tmem) : "r"(TMEMP));
    if (wid == 0) TCGEN05_RELINQ();

    // Load resident B: 4 K64 sub-tiles of 16KB
    {
        const __half* BHb = WH + (size_t)(bcolW + lr) * K + c16 * 8;
#pragma unroll
        for (int kt = 0; kt < 4; kt++) {
#pragma unroll
            for (int i = 0; i < 4; i++) {
                size_t ro = (size_t)(i * 32) * K + kt * 64;
                uint32_t so = (uint32_t)kt * 16384 + swr + (uint32_t)i * 4096;
                *(uint4*)(smem + 1024 + so) = *(const uint4*)(BHb + ro);
            }
        }
    }
    FENCE_PROXY_ASYNC();
    __syncthreads();

    // Prefetch first A chunk (m=cid, kt=0)
    uint4 ua_cur[4];
    {
        const __half* A0 = A + (size_t)(cid * 128 + lr) * K + c16 * 8;
#pragma unroll
        for (int i = 0; i < 4; i++)
            ua_cur[i] = *(const uint4*)(A0 + (size_t)(i * 32) * K);
    }

    int g = 0;
    for (int m = cid; m < MT_TILES; m += CPC) {
#pragma unroll 1
        for (int kt = 0; kt < 4; kt++, g++) {
            const int s = g & 1;

            uint4 ua_nxt[4];
            int nm = (kt < 3) ? m : m + CPC;
            int nk = (kt < 3) ? kt + 1 : 0;
            bool have_next = (nm < MT_TILES);
            if (have_next) {
                const __half* An = A + (size_t)(nm * 128 + lr) * K + c16 * 8 + nk * 64;
#pragma unroll
                for (int i = 0; i < 4; i++)
                    ua_nxt[i] = *(const uint4*)(An + (size_t)(i * 32) * K);
            }

            if (g >= 2) {
                MBARRIER_WAIT_PARITY(s ? MBAR1 : MBAR0, ((g >> 1) - 1) & 1);
            }
            char* sb = smem + 1024 + 65536 + s * ASTAGE;
#pragma unroll
            for (int i = 0; i < 4; i++)
                *(uint4*)(sb + swr + i * 4096) = ua_cur[i];
            FENCE_PROXY_ASYNC();
            __syncthreads();

            if (wid == 0) {
                if (elect_one_pred()) {
                    uint64_t dah = make_sw128_desc(AST + s * ASTAGE);
                    uint64_t dbh = make_sw128_desc(BH_S + kt * 16384);
#pragma unroll
                    for (int ks = 0; ks < 4; ks++) {
                        TCGEN05_MMA_F16_SS(tmem, dah + ks * 2, dbh + ks * 2,
                                           TCG_IDESC, (kt > 0) || (ks > 0));
                    }
                    TCGEN05_COMMIT(s ? MBAR1 : MBAR0);
                }
            }

            if (have_next) {
#pragma unroll
                for (int i = 0; i < 4; i++) ua_cur[i] = ua_nxt[i];
            }
        }

        {
            int gl = g - 1;
            MBARRIER_WAIT_PARITY((gl & 1) ? MBAR1 : MBAR0, (gl >> 1) & 1);
            TCGEN05_FENCE_AFTER();

            int colbase = (wid >> 2) * 64;
            uint32_t d0[32], d1[32];
            TCGEN05_LD32(d0, tmem + colbase);
            TCGEN05_LD32(d1, tmem + colbase + 32);
            TCGEN05_WAIT_LD();
            TCGEN05_FENCE_BEFORE();

            int r = m * 128 + (wid & 3) * 32 + lane;
            size_t cb = (size_t)r * N + bcolC + colbase;
            const float* bb = bias + bcolW + colbase;
#pragma unroll
            for (int c = 0; c < 32; c += 4) {
                float4 o;
                o.x = __uint_as_float(d0[c + 0]) + bb[c + 0];
                o.y = __uint_as_float(d0[c + 1]) + bb[c + 1];
                o.z = __uint_as_float(d0[c + 2]) + bb[c + 2];
                o.w = __uint_as_float(d0[c + 3]) + bb[c + 3];
                if (outH) epi_store4<RELU, 1>(C, cb + c, o);
                else      epi_store4<RELU, 0>(C, cb + c, o);
            }
#pragma unroll
            for (int c = 0; c < 32; c += 4) {
                float4 o;
                o.x = __uint_as_float(d1[c + 0]) + bb[32 + c + 0];
                o.y = __uint_as_float(d1[c + 1]) + bb[32 + c + 1];
                o.z = __uint_as_float(d1[c + 2]) + bb[32 + c + 2];
                o.w = __uint_as_float(d1[c + 3]) + bb[32 + c + 3];
                if (outH) epi_store4<RELU, 1>(C, cb + 32 + c, o);
                else      epi_store4<RELU, 0>(C, cb + 32 + c, o);
            }
            __syncthreads();
        }
    }

    __syncthreads();
    if (tid == 0) { MBARRIER_INVAL(MBAR0); MBARRIER_INVAL(MBAR1); }
    __syncthreads();
    if (wid == 0) TCGEN05_DEALLOC(tmem, 128);

#else  // SIMT fallback
    float (*As)[132] = (float(*)[132])(smem);
    float (*Bs)[132] = (float(*)[132])(smem + 64 * 132 * 4);
    int ty = (tid >> 4) * 8;
    int tx = (tid & 15) * 8;

    for (int m = cid; m < MT_TILES; m += CPC) {
        int brow = m * 128;
        float acc[8][8];
#pragma unroll
        for (int i = 0; i < 8; i++)
#pragma unroll
            for (int j = 0; j < 8; j++) acc[i][j] = 0.f;

        for (int kt = 0; kt < 4; kt++) {
            __syncthreads();
#pragma unroll
            for (int i = 0; i < 4; i++) {
                int row = i * 32 + lr;
                size_t aro = (size_t)(brow + row) * K + kt * 64 + c16 * 8;
                size_t bro = (size_t)(bcolW + row) * K + kt * 64 + c16 * 8;
#pragma unroll
                for (int j = 0; j < 8; j++) {
                    As[c16 * 8 + j][row] = __half2float(A[aro + j]);
                    Bs[c16 * 8 + j][row] = __half2float(WH[bro + j]);
                }
            }
            __syncthreads();
#pragma unroll 16
            for (int k = 0; k < 64; k++) {
                float av[8], bv[8];
#pragma unroll
                for (int i = 0; i < 8; i++) { av[i] = As[k][ty + i]; bv[i] = Bs[k][tx + i]; }
#pragma unroll
                for (int i = 0; i < 8; i++)
#pragma unroll
                    for (int j = 0; j < 8; j++)
                        acc[i][j] += av[i] * bv[j];
            }
        }
        int row = brow + ty;
#pragma unroll
        for (int i = 0; i < 8; i++)
#pragma unroll
            for (int j = 0; j < 8; j++) {
                float v = acc[i][j] + bias[bcolW + tx + j];
                if (RELU) v = fmaxf(v, 0.f);
                size_t oidx = (size_t)(row + i) * N + bcolC + tx + j;
                if (outH) ((__half*)C)[oidx] = __float2half_rn(v);
                else      C[oidx] = v;
            }
        __syncthreads();
    }
#endif
}

// ---------------------------------------------------------------------------
// Fused weight transpose + fp16 convert (all 6 types, 3 layers per launch)
// ---------------------------------------------------------------------------
__global__ void transplit_all(const float* __restrict__ Wval, const float* __restrict__ Woff,
                              const float* __restrict__ Wattn, const float* __restrict__ Wout,
                              const float* __restrict__ W1, const float* __restrict__ W2,
                              __half* __restrict__ wth, int layer0) {
    int type  = blockIdx.y;
    int layer = layer0 + blockIdx.z;
    const float* W; int K, N, off;
    switch (type) {
        case 0: W = Wval  + (size_t)layer * 65536;  K = 256;  N = 256;  off = WT_VAL;  break;
        case 1: W = Woff  + (size_t)layer * 65536;  K = 256;  N = 256;  off = WT_OFF;  break;
        case 2: W = Wattn + (size_t)layer * 32768;  K = 256;  N = 128;  off = WT_ATTN; break;
        case 3: W = Wout  + (size_t)layer * 65536;  K = 256;  N = 256;  off = WT_OUT;  break;
        case 4: W = W1    + (size_t)layer * 262144; K = 256;  N = 1024; off = WT_W1;   break;
        default: W = W2   + (size_t)layer * 262144; K = 1024; N = 256;  off = WT_W2;   break;
    }
    int tK = K >> 5, tN = N >> 5;
    int t = blockIdx.x;
    if (t >= tK * tN) return;
    int k0 = (t % tK) * 32, n0 = (t / tK) * 32;

    __shared__ float tile[32][33];
    tile[threadIdx.y][threadIdx.x] = W[(size_t)(k0 + threadIdx.y) * N + n0 + threadIdx.x];
    __syncthreads();
    float v = tile[threadIdx.x][threadIdx.y];
    size_t o = (size_t)layer * WT_LAYER + off + (size_t)(n0 + threadIdx.y) * K + k0 + threadIdx.x;
    wth[o] = __float2half_rn(v);
}

// Bias concat: g_biasva[l][0..255]=bval, [256..511]=boff, [512..639]=battn
__global__ void biascat_kernel(const float* __restrict__ bval,
                               const float* __restrict__ boff,
                               const float* __restrict__ battn,
                               float* __restrict__ dst) {
    int l = blockIdx.x, j = threadIdx.x;
    float v;
    if (j < 256)      v = bval[l * 256 + j];
    else if (j < 512) v = boff[l * 256 + j - 256];
    else              v = battn[l * 128 + j - 512];
    dst[l * 640 + j] = v;
}

// ---------------------------------------------------------------------------
// Flatten pair of levels: src [B, D, h, w] -> out [B, S, D]; pos(h) + level_embed.
// Also seeds fp16 mirrors: outh = fp16(out), qh = fp16(out+pos).
// ---------------------------------------------------------------------------
__global__ void flatten_pair(const float* __restrict__ sA, const float* __restrict__ pA,
                             int hwA, int stA, int lvA,
                             const float* __restrict__ sB, const float* __restrict__ pB,
                             int hwB, int stB, int lvB,
                             const float* __restrict__ lemb,
                             float* __restrict__ out, __half* __restrict__ posouth,
                             __half* __restrict__ outh, __half* __restrict__ qh) {
    __shared__ float ts[32][33];
    __shared__ float tp[32][33];
    int px = blockIdx.x;
    const float *src, *pos; int hw, start, level, p0;
    int tA = hwA >> 5;
    if (px < tA) { src = sA; pos = pA; hw = hwA; start = stA; level = lvA; p0 = px * 32; }
    else         { src = sB; pos = pB; hw = hwB; start = stB; level = lvB; p0 = (px - tA) * 32; }

    int b  = blockIdx.z;
    int d0 = blockIdx.y * 32;
    int tx = threadIdx.x, ty = threadIdx.y;

    const float* sp = src + ((size_t)b * D_MODEL + d0 + ty) * hw + p0;
    const float* pp = pos + ((size_t)b * D_MODEL + d0 + ty) * hw + p0;
    ts[ty][tx] = sp[tx];
    tp[ty][tx] = pp[tx];
    __syncthreads();

    int d = d0 + tx;
    float le = lemb[level * D_MODEL + d];
    size_t srow = (size_t)b * S_TOTAL + start + p0 + ty;
    float v = ts[tx][ty];
    float p = tp[tx][ty] + le;
    out[srow * D_MODEL + d]      = v;
    posouth[srow * D_MODEL + d]  = __float2half_rn(p);
    outh[srow * D_MODEL + d]     = __float2half_rn(v);
    qh[srow * D_MODEL + d]       = __float2half_rn(v + p);
}

// ---------------------------------------------------------------------------
// Residual + LayerNorm: out = LN(xh + r) * gamma + beta. One warp per row.
// ---------------------------------------------------------------------------
__global__ void resid_ln_kernel(const __half* __restrict__ Xh, const float* __restrict__ R,
                                const float* __restrict__ g, const float* __restrict__ bt,
                                float* __restrict__ O, __half* __restrict__ Oh,
                                const __half* __restrict__ Ph, __half* __restrict__ Qh,
                                int rows) {
    int warp = (blockIdx.x * blockDim.x + threadIdx.x) >> 5;
    int lane = threadIdx.x & 31;
    if (warp >= rows) return;
    const __half* xr = Xh + (size_t)warp * D_MODEL;
    const float*  rr = R  + (size_t)warp * D_MODEL;

    float v[8];
    float s = 0.f, s2 = 0.f;
#pragma unroll
    for (int u = 0; u < 2; u++) {
        uint2 ux = *(const uint2*)(xr + lane * 4 + u * 128);
        float2 xa = __half22float2(*(__half2*)&ux.x);
        float2 xb = __half22float2(*(__half2*)&ux.y);
        float4 c = *(const float4*)(rr + lane * 4 + u * 128);
        float t0 = xa.x + c.x, t1 = xa.y + c.y, t2 = xb.x + c.z, t3 = xb.y + c.w;
        v[u * 4 + 0] = t0; v[u * 4 + 1] = t1; v[u * 4 + 2] = t2; v[u * 4 + 3] = t3;
        s += t0 + t1 + t2 + t3;
        s2 += t0 * t0 + t1 * t1 + t2 * t2 + t3 * t3;
    }
#pragma unroll
    for (int o = 16; o > 0; o >>= 1) {
        s  += __shfl_xor_sync(0xffffffffu, s, o);
        s2 += __shfl_xor_sync(0xffffffffu, s2, o);
    }
    float mean = s * (1.f / D_MODEL);
    float var  = s2 * (1.f / D_MODEL) - mean * mean;
    float inv  = rsqrtf(var + 1e-5f);
#pragma unroll
    for (int u = 0; u < 2; u++) {
        int d = lane * 4 + u * 128;
        float4 o4;
        o4.x = (v[u * 4 + 0] - mean) * inv * g[d + 0] + bt[d + 0];
        o4.y = (v[u * 4 + 1] - mean) * inv * g[d + 1] + bt[d + 1];
        o4.z = (v[u * 4 + 2] - mean) * inv * g[d + 2] + bt[d + 2];
        o4.w = (v[u * 4 + 3] - mean) * inv * g[d + 3] + bt[d + 3];
        *(float4*)(O + (size_t)warp * D_MODEL + d) = o4;

        __half2 h0 = __halves2half2(__float2half_rn(o4.x), __float2half_rn(o4.y));
        __half2 h1 = __halves2half2(__float2half_rn(o4.z), __float2half_rn(o4.w));
        uint2 uo; uo.x = *(uint32_t*)&h0; uo.y = *(uint32_t*)&h1;
        *(uint2*)(Oh + (size_t)warp * D_MODEL + d) = uo;

        if (Qh) {
            uint2 up = *(const uint2*)(Ph + (size_t)warp * D_MODEL + d);
            float2 pa = __half22float2(*(__half2*)&up.x);
            float2 pb = __half22float2(*(__half2*)&up.y);
            __half2 q0 = __halves2half2(__float2half_rn(o4.x + pa.x),
                                        __float2half_rn(o4.y + pa.y));
            __half2 q1 = __halves2half2(__float2half_rn(o4.z + pb.x),
                                        __float2half_rn(o4.w + pb.y));
            uint2 uq; uq.x = *(uint32_t*)&q0; uq.y = *(uint32_t*)&q1;
            *(uint2*)(Qh + (size_t)warp * D_MODEL + d) = uq;
        }
    }
}

// ---------------------------------------------------------------------------
// Deformable sampling, fp16 values in, fp16 samp out. One warp per (token, head).
// ---------------------------------------------------------------------------
__constant__ int c_lw[4]     = {128, 64, 32, 16};
__constant__ int c_lstart[4] = {0, 16384, 20480, 21504};

__global__ void sample_kernel(const __half* __restrict__ Valh,
                              const float* __restrict__ OA,
                              __half* __restrict__ Samph) {
    __shared__ int2 tab[8][16][4];
    int gw   = (blockIdx.x * blockDim.x + threadIdx.x) >> 5;
    int lane = threadIdx.x & 31;
    int wpb  = threadIdx.x >> 5;
    if (gw >= M_TOT * NH) return;
    int h   = gw & 7;
    int tok = gw >> 3;
    int s   = tok % S_TOTAL;
    int b   = tok / S_TOTAL;

    int wt, st, sh;
    if (s < 16384)      { wt = 128; st = 0;     sh = 7; }
    else if (s < 20480) { wt = 64;  st = 16384; sh = 6; }
    else if (s < 21504) { wt = 32;  st = 20480; sh = 5; }
    else                { wt = 16;  st = 21504; sh = 4; }
    int sl = s - st;
    int iy = sl >> sh;
    int ix = sl - (iy << sh);
    float refx = (ix + 0.5f) / (float)wt;
    float refy = (iy + 0.5f) / (float)wt;

    size_t rb = (size_t)tok;

    float lv = (lane < 16) ? OA[rb * 384 + 256 + h * 16 + lane] : -1e30f;
    float m = lv;
#pragma unroll
    for (int o = 8; o > 0; o >>= 1) m = fmaxf(m, __shfl_xor_sync(0xffffffffu, m, o));
    float e = (lane < 16) ? expf(lv - m) : 0.f;
    float ssum = e;
#pragma unroll
    for (int o = 8; o > 0; o >>= 1) ssum += __shfl_xor_sync(0xffffffffu, ssum, o);
    float aw = e / ssum;

    if (lane < 16) {
        int l   = lane >> 2;
        int wl  = c_lw[l];
        int stl = c_lstart[l];
        float ox = OA[rb * 384 + (size_t)(h * 16 + lane) * 2 + 0];
        float oy = OA[rb * 384 + (size_t)(h * 16 + lane) * 2 + 1];
        float x = refx * (float)wl + ox - 0.5f;
        float y = refy * (float)wl + oy - 0.5f;
        float xf = floorf(x), yf = floorf(y);
        float lx = x - xf, ly = y - yf;
        int x0 = (int)xf, y0 = (int)yf;
        int x1 = x0 + 1, y1 = y0 + 1;
        bool okx0 = (x0 >= 0) & (x0 < wl);
        bool okx1 = (x1 >= 0) & (x1 < wl);
        bool oky0 = (y0 >= 0) & (y0 < wl);
        bool oky1 = (y1 >= 0) & (y1 < wl);
        int cx0 = min(max(x0, 0), wl - 1), cx1 = min(max(x1, 0), wl - 1);
        int cy0 = min(max(y0, 0), wl - 1), cy1 = min(max(y1, 0), wl - 1);
        float w0 = (1.f - lx) * (1.f - ly) * aw * ((okx0 && oky0) ? 1.f : 0.f);
        float w1 = lx * (1.f - ly) * aw * ((okx1 && oky0) ? 1.f : 0.f);
        float w2 = (1.f - lx) * ly * aw * ((okx0 && oky1) ? 1.f : 0.f);
        float w3 = lx * ly * aw * ((okx1 && oky1) ? 1.f : 0.f);
        tab[wpb][lane][0] = make_int2(stl + cy0 * wl + cx0, __float_as_int(w0));
        tab[wpb][lane][1] = make_int2(stl + cy0 * wl + cx1, __float_as_int(w1));
        tab[wpb][lane][2] = make_int2(stl + cy1 * wl + cx0, __float_as_int(w2));
        tab[wpb][lane][3] = make_int2(stl + cy1 * wl + cx1, __float_as_int(w3));
    }
    __syncwarp();

    int t   = lane >> 3;
    int ch4 = lane & 7;
    const __half* vb = Valh + (size_t)b * S_TOTAL * 256 + h * 32 + ch4 * 4;
    float4 acc = make_float4(0.f, 0.f, 0.f, 0.f);
#pragma unroll
    for (int j = 0; j < 16; j++) {
        int2 ee = tab[wpb][j][t];
        uint2 u = *(const uint2*)(vb + (size_t)ee.x * 256);
        __half2 p0 = *(__half2*)&u.x;
        __half2 p1 = *(__half2*)&u.y;
        float2 f0 = __half22float2(p0);
        float2 f1 = __half22float2(p1);
        float f = __int_as_float(ee.y);
        acc.x += f * f0.x; acc.y += f * f0.y;
        acc.z += f * f1.x; acc.w += f * f1.y;
    }
#pragma unroll
    for (int msk = 8; msk <= 16; msk <<= 1) {
        acc.x += __shfl_xor_sync(0xffffffffu, acc.x, msk);
        acc.y += __shfl_xor_sync(0xffffffffu, acc.y, msk);
        acc.z += __shfl_xor_sync(0xffffffffu, acc.z, msk);
        acc.w += __shfl_xor_sync(0xffffffffu, acc.w, msk);
    }
    if (lane < 8) {
        __half2 h0 = __halves2half2(__float2half_rn(acc.x), __float2half_rn(acc.y));
        __half2 h1 = __halves2half2(__float2half_rn(acc.z), __float2half_rn(acc.w));
        uint2 u; u.x = *(uint32_t*)&h0; u.y = *(uint32_t*)&h1;
        ((uint2*)(Samph + (size_t)tok * 256 + h * 32))[ch4] = u;
    }
}

// ---------------------------------------------------------------------------
// Host orchestration
// ---------------------------------------------------------------------------
extern "C" void kernel_launch(void* const* d_in, const int* in_sizes, int n_in,
                              void* d_out, int out_size) {
    const float* src[4];
    const float* posin[4];
    bool interleaved = (in_sizes[1] == in_sizes[0]);
    for (int l = 0; l < 4; l++) {
        if (interleaved) {
            src[l]   = (const float*)d_in[2 * l];
            posin[l] = (const float*)d_in[2 * l + 1];
        } else {
            src[l]   = (const float*)d_in[l];
            posin[l] = (const float*)d_in[4 + l];
        }
    }
    const float* lemb  = (const float*)d_in[8];
    const float* Woff  = (const float*)d_in[9];
    const float* boff  = (const float*)d_in[10];
    const float* Wattn = (const float*)d_in[11];
    const float* battn = (const float*)d_in[12];
    const float* Wval  = (const float*)d_in[13];
    const float* bval  = (const float*)d_in[14];
    const float* Wout  = (const float*)d_in[15];
    const float* bout  = (const float*)d_in[16];
    const float* ln1s  = (const float*)d_in[17];
    const float* ln1b  = (const float*)d_in[18];
    const float* W1    = (const float*)d_in[19];
    const float* b1    = (const float*)d_in[20];
    const float* W2    = (const float*)d_in[21];
    const float* b2    = (const float*)d_in[22];
    const float* ln2s  = (const float*)d_in[23];
    const float* ln2b  = (const float*)d_in[24];

    float* out = (float*)d_out;

    float *offawl, *biasva;
    __half *posh, *outh, *qh, *valh, *samph, *tmph, *ffh, *wth;
    cudaGetSymbolAddress((void**)&posh,   g_posh);
    cudaGetSymbolAddress((void**)&outh,   g_outh);
    cudaGetSymbolAddress((void**)&qh,     g_qh);
    cudaGetSymbolAddress((void**)&valh,   g_valh);
    cudaGetSymbolAddress((void**)&offawl, g_offawl);
    cudaGetSymbolAddress((void**)&samph,  g_samph);
    cudaGetSymbolAddress((void**)&tmph,   g_tmph);
    cudaGetSymbolAddress((void**)&ffh,    g_ffh);
    cudaGetSymbolAddress((void**)&biasva, g_biasva);
    cudaGetSymbolAddress((void**)&wth,    g_wth);

    cudaFuncSetAttribute((tc_gemm_h<0,1>),      cudaFuncAttributeMaxDynamicSharedMemorySize, TCGH_SMEM);
    cudaFuncSetAttribute((tc_gemm_pers<0,0,1>), cudaFuncAttributeMaxDynamicSharedMemorySize, PERS_SMEM_H);
    cudaFuncSetAttribute((tc_gemm_pers<0,1,0>), cudaFuncAttributeMaxDynamicSharedMemorySize, PERS_SMEM_H);
    cudaFuncSetAttribute((tc_gemm_pers<1,1,0>), cudaFuncAttributeMaxDynamicSharedMemorySize, PERS_SMEM_H);

    // Prologue: 5 launches
    transplit_all<<<dim3(256, 6, 3), dim3(32, 32)>>>(Wval, Woff, Wattn, Wout, W1, W2,
                                                     wth, 0);
    transplit_all<<<dim3(256, 6, 3), dim3(32, 32)>>>(Wval, Woff, Wattn, Wout, W1, W2,
                                                     wth, 3);
    biascat_kernel<<<NLAYERS, 640>>>(bval, boff, battn, biasva);
    flatten_pair<<<dim3(16384/32 + 4096/32, 8, BATCH), dim3(32, 32)>>>(
        src[0], posin[0], 16384, 0, 0, src[1], posin[1], 4096, 16384, 1,
        lemb, out, posh, outh, qh);
    flatten_pair<<<dim3(1024/32 + 256/32, 8, BATCH), dim3(32, 32)>>>(
        src[2], posin[2], 1024, 20480, 2, src[3], posin[3], 256, 21504, 3,
        lemb, out, posh, outh, qh);

    for (int i = 0; i < NLAYERS; i++) {
        const __half* bh = wth + (size_t)i * WT_LAYER;
        // FUSED: val(fp16) = outh@Wval+bval  AND  [off|awl](f32) = qh@[Woff|Wattn]+biases
        // 5 col groups x 59 CTAs = 295 CTAs
        tc_gemm_pers<0,0,1><<<295, 256, PERS_SMEM_H>>>(outh, qh, bh + WT_VAL,
                                                       biasva + i * 640,
                                                       (float*)valh, offawl, 0, 59);
        // deformable sampling (fp16 values in, fp16 samp out)
        sample_kernel<<<M_TOT * NH / 8, 256>>>(valh, offawl, samph);
        // attn out (fp16) = samph @ Wout + bout      (2 cols x 148 CTAs)
        tc_gemm_pers<0,1,0><<<296, 256, PERS_SMEM_H>>>(samph, nullptr, bh + WT_OUT,
                                                       bout + i * 256,
                                                       (float*)tmph, nullptr, 256, 148);
        // out = LN(out + attn); emit outh
        resid_ln_kernel<<<(M_TOT + 7) / 8, 256>>>(tmph, out, ln1s + i * 256,
                                                  ln1b + i * 256, out, outh,
                                                  nullptr, nullptr, M_TOT);
        // h(fp16) = relu(outh @ W1 + b1)             (8 cols x 37 CTAs)
        tc_gemm_pers<1,1,0><<<296, 256, PERS_SMEM_H>>>(outh, nullptr, bh + WT_W1,
                                                       b1 + i * 1024,
                                                       (float*)ffh, nullptr, 1024, 37);
        // ff (fp16) = h(fp16) @ W2 + b2              (K=1024: streaming)
        tc_gemm_h<0,1><<<dim3(M_TOT / 128, 2), 256, TCGH_SMEM>>>(ffh, bh + WT_W2,
                                                                 b2 + i * 256, (float*)tmph,
                                                                 M_TOT, 256, 1024);
        // out = LN(out + ff); emit outh + qh for next layer
        resid_ln_kernel<<<(M_TOT + 7) / 8, 256>>>(tmph, out, ln2s + i * 256,
                                                  ln2b + i * 256, out, outh,
                                                  posh, qh, M_TOT);
    }
}